// round 16
// baseline (speedup 1.0000x reference)
#include <cuda_runtime.h>
#include <cuda_fp16.h>
#include <cstdint>

// ---------------------------------------------------------------------------
// Problem constants
// ---------------------------------------------------------------------------
#define N_ROWS  32768
#define DIM     512
#define KCODES  512
#define Q_ELEMS (N_ROWS * DIM)
#define LOSS_OFF Q_ELEMS
#define OH_OFF   (Q_ELEMS + 1)
#define IDX_OFF  (OH_OFF + N_ROWS * KCODES)

#define NB_QO 2048     // blocks for quantized writer
#define NB_MG 128      // blocks for merge (+loss partials)

// Fused prep kernel block ranges
#define NB_CONVA (N_ROWS / 4)                 // 8192
#define NB_CONVB (KCODES * DIM / 8 / 256)     // 128
#define NB_CN    2                            // colnorm: 2 x 256 = 512 cols
#define NB_EN    (KCODES / 8)                 // 64 (8 rows per block)
#define NB_PREP  (NB_CONVA + NB_CONVB + NB_CN + NB_EN)

// GEMM tiling: M=128 x N=128 per CTA, BK=32, fused 3 products, 2 CTAs/SM.
#define MT   128
#define NTC  128
#define BK   32
#define NKCH (DIM / BK)          // 16
#define RBLK (N_ROWS / MT)       // 256
#define CBLK (KCODES / NTC)      // 4

#define TSTRIDE 40               // 32 + 8 pad (rows stride 80B, conflict-free)
#define AT_B   (MT * TSTRIDE * 2)        // 10240
#define AH_OFF 0
#define AL_OFF AT_B
#define BH_OFF (2 * AT_B)
#define BL_OFF (3 * AT_B)
#define STAGE_B (4 * AT_B)               // 40960
#define CN_OFF  (2 * STAGE_B)            // 81920
#define RED_OFF (CN_OFF + 512)           // 82432
#define SMEM_DYN (RED_OFF + 2 * 128 * 8) // 84480  (2 CTAs/SM)

// ---------------------------------------------------------------------------
// Device scratch
// ---------------------------------------------------------------------------
__device__ __align__(16) __half g_Ah[(size_t)N_ROWS * DIM];
__device__ __align__(16) __half g_Al[(size_t)N_ROWS * DIM];
__device__ __align__(16) __half g_Bh[(size_t)KCODES * DIM];
__device__ __align__(16) __half g_Bl[(size_t)KCODES * DIM];
__device__ float  g_rownorm[N_ROWS];
__device__ float  g_colnorm[KCODES];   // dim=0 norm (reference's buggy norm)
__device__ float  g_embnorm[KCODES];   // dim=1 norm (true row norm, loss only)
__device__ unsigned long long g_part[(size_t)CBLK * N_ROWS];
__device__ int    g_idx[N_ROWS];
__device__ double g_partial[NB_MG];

// ---------------------------------------------------------------------------
// PTX helpers (compute_100-legal)
// ---------------------------------------------------------------------------
__device__ __forceinline__ unsigned smem_u32(const void* p) {
    unsigned a;
    asm("{ .reg .u64 t; cvta.to.shared.u64 t, %1; cvt.u32.u64 %0, t; }" : "=r"(a) : "l"(p));
    return a;
}
__device__ __forceinline__ void cp16(unsigned dst, const void* src) {
    asm volatile("cp.async.cg.shared.global [%0], [%1], 16;" :: "r"(dst), "l"(src));
}
__device__ __forceinline__ void cp_commit() { asm volatile("cp.async.commit_group;"); }
__device__ __forceinline__ void cp_wait1()  { asm volatile("cp.async.wait_group 1;"); }
__device__ __forceinline__ void cp_wait0()  { asm volatile("cp.async.wait_group 0;"); }

__device__ __forceinline__ void ldmx4(unsigned& r0, unsigned& r1, unsigned& r2, unsigned& r3,
                                      unsigned addr) {
    asm volatile("ldmatrix.sync.aligned.m8n8.x4.shared.b16 {%0,%1,%2,%3}, [%4];"
                 : "=r"(r0), "=r"(r1), "=r"(r2), "=r"(r3) : "r"(addr));
}
__device__ __forceinline__ void mma16816(float& c0, float& c1, float& c2, float& c3,
                                         unsigned a0, unsigned a1, unsigned a2, unsigned a3,
                                         unsigned b0, unsigned b1) {
    asm volatile("mma.sync.aligned.m16n8k16.row.col.f32.f16.f16.f32 "
                 "{%0,%1,%2,%3}, {%4,%5,%6,%7}, {%8,%9}, {%0,%1,%2,%3};"
                 : "+f"(c0), "+f"(c1), "+f"(c2), "+f"(c3)
                 : "r"(a0), "r"(a1), "r"(a2), "r"(a3), "r"(b0), "r"(b1));
}

// ---------------------------------------------------------------------------
// fp32 -> (fp16 hi, fp16 lo)
// ---------------------------------------------------------------------------
__device__ __forceinline__ unsigned pack2(float a, float b) {
    unsigned short ha = __half_as_ushort(__float2half_rn(a));
    unsigned short hb = __half_as_ushort(__float2half_rn(b));
    return (unsigned)ha | ((unsigned)hb << 16);
}

// ---------------------------------------------------------------------------
// Fused prep: convA+rownorm | convertB | colnorm | embnorm by block range.
// Bodies byte-identical to the round-15 passing kernel.
// ---------------------------------------------------------------------------
__global__ __launch_bounds__(256) void k_prep(const float* __restrict__ lat,
                                              const float* __restrict__ emb) {
    __shared__ float sx[4][DIM];
    const int tid = threadIdx.x;
    const int bx  = blockIdx.x;

    if (bx < NB_CONVA) {
        const int nl  = tid >> 6;
        const int c   = (tid & 63) * 8;
        const size_t n = (size_t)bx * 4 + nl;
        const size_t off = n * DIM + c;

        const float4* s4 = (const float4*)(lat + off);
        float4 v0 = s4[0], v1 = s4[1];
        float x[8] = {v0.x, v0.y, v0.z, v0.w, v1.x, v1.y, v1.z, v1.w};
        float l[8];
        #pragma unroll
        for (int j = 0; j < 8; j++) {
            sx[nl][c + j] = x[j];
            l[j] = x[j] - __half2float(__float2half_rn(x[j]));
        }
        uint4 hi = make_uint4(pack2(x[0], x[1]), pack2(x[2], x[3]),
                              pack2(x[4], x[5]), pack2(x[6], x[7]));
        uint4 lo = make_uint4(pack2(l[0], l[1]), pack2(l[2], l[3]),
                              pack2(l[4], l[5]), pack2(l[6], l[7]));
        *(uint4*)(g_Ah + off) = hi;
        *(uint4*)(g_Al + off) = lo;

        __syncthreads();
        const int wid  = tid >> 5;
        const int lane = tid & 31;
        if (wid < 4) {
            float s = 0.f;
            for (int t = lane; t < DIM; t += 32) {
                float v = sx[wid][t];
                s += v * v;
            }
            #pragma unroll
            for (int o = 16; o > 0; o >>= 1) s += __shfl_xor_sync(0xffffffffu, s, o);
            if (lane == 0) g_rownorm[(size_t)bx * 4 + wid] = s;
        }
    } else if (bx < NB_CONVA + NB_CONVB) {
        size_t g = (size_t)(bx - NB_CONVA) * 256 + tid;
        size_t off = g * 8;
        const float4* s4 = (const float4*)(emb + off);
        float4 v0 = s4[0], v1 = s4[1];
        float x[8] = {v0.x, v0.y, v0.z, v0.w, v1.x, v1.y, v1.z, v1.w};
        float l[8];
        #pragma unroll
        for (int j = 0; j < 8; j++)
            l[j] = x[j] - __half2float(__float2half_rn(x[j]));
        uint4 hi = make_uint4(pack2(x[0], x[1]), pack2(x[2], x[3]),
                              pack2(x[4], x[5]), pack2(x[6], x[7]));
        uint4 lo = make_uint4(pack2(l[0], l[1]), pack2(l[2], l[3]),
                              pack2(l[4], l[5]), pack2(l[6], l[7]));
        *(uint4*)(g_Bh + off) = hi;
        *(uint4*)(g_Bl + off) = lo;
    } else if (bx < NB_CONVA + NB_CONVB + NB_CN) {
        int k = (bx - NB_CONVA - NB_CONVB) * 256 + tid;
        float s = 0.f;
        for (int j = 0; j < KCODES; j++) {
            float v = emb[(size_t)j * DIM + k];
            s += v * v;
        }
        g_colnorm[k] = s;
    } else {
        const int wid  = tid >> 5;
        const int lane = tid & 31;
        int warp = (bx - NB_CONVA - NB_CONVB - NB_CN) * 8 + wid;
        const float* e = emb + (size_t)warp * DIM;
        float s = 0.f;
        for (int t = lane; t < DIM; t += 32) {
            float v = e[t];
            s += v * v;
        }
        #pragma unroll
        for (int o = 16; o > 0; o >>= 1) s += __shfl_xor_sync(0xffffffffu, s, o);
        if (lane == 0) g_embnorm[warp] = s;
    }
}

// ---------------------------------------------------------------------------
// GEMM + argmin: 128x128 tile, BK=32, 2 CTAs/SM. Product-major MMA ordering:
// consecutive MMAs target different accumulators (breaks the 3-deep
// same-accumulator RAW chain). Per-accumulator addition order is UNCHANGED
// (AhBh, AlBh, AhBl per ks) => bit-identical results to round 15.
// ---------------------------------------------------------------------------
__global__ __launch_bounds__(256, 2) void k_gemm_argmin() {
    extern __shared__ char smem[];
    const unsigned S = smem_u32(smem);

    const int tid  = threadIdx.x;
    const int wid  = tid >> 5;
    const int lane = tid & 31;
    const int wm   = wid >> 1;
    const int wn   = wid & 1;
    const int quad = lane >> 2;
    const int qt   = lane & 3;
    const int cb   = blockIdx.x & 3;
    const int rb   = blockIdx.x >> 2;
    const int row0 = rb * MT;
    const int col0 = cb * NTC;

    float* s_cn = (float*)(smem + CN_OFF);
    unsigned long long* s_red = (unsigned long long*)(smem + RED_OFF);

    if (tid < NTC) s_cn[tid] = g_colnorm[col0 + tid];

    const __half* Ah = g_Ah + (size_t)row0 * DIM;
    const __half* Al = g_Al + (size_t)row0 * DIM;
    const __half* Bh = g_Bh + (size_t)col0 * DIM;
    const __half* Bl = g_Bl + (size_t)col0 * DIM;

    float acc[2][8][4];
    #pragma unroll
    for (int mt = 0; mt < 2; mt++)
        #pragma unroll
        for (int nt = 0; nt < 8; nt++)
            #pragma unroll
            for (int j = 0; j < 4; j++) acc[mt][nt][j] = 0.f;

    auto load_chunk = [&](int i, int buf) {
        const int kc = i * BK;
        const unsigned st = S + buf * STAGE_B;
        #pragma unroll
        for (int j = 0; j < 2; j++) {
            int id = tid + j * 256;          // 0..511
            int r = id >> 2, c = (id & 3) * 8;
            unsigned d = (unsigned)((r * TSTRIDE + c) * 2);
            cp16(st + AH_OFF + d, Ah + (size_t)r * DIM + kc + c);
            cp16(st + AL_OFF + d, Al + (size_t)r * DIM + kc + c);
            cp16(st + BH_OFF + d, Bh + (size_t)r * DIM + kc + c);
            cp16(st + BL_OFF + d, Bl + (size_t)r * DIM + kc + c);
        }
        cp_commit();
    };

    load_chunk(0, 0);

    const int g  = lane >> 3;
    const int l8 = lane & 7;

    for (int i = 0; i < NKCH; i++) {
        const int buf = i & 1;
        if (i + 1 < NKCH) { load_chunk(i + 1, buf ^ 1); cp_wait1(); }
        else             { cp_wait0(); }
        __syncthreads();

        const unsigned st = S + buf * STAGE_B;

        #pragma unroll
        for (int ks = 0; ks < 2; ks++) {
            const int k0 = ks * 16;
            // load ALL fragments for this ks first
            unsigned ah[2][4], al[2][4];
            #pragma unroll
            for (int mt = 0; mt < 2; mt++) {
                int r = wm * 32 + mt * 16 + ((g & 1) << 3) + l8;
                int c = k0 + ((g >> 1) << 3);
                unsigned d = (unsigned)((r * TSTRIDE + c) * 2);
                ldmx4(ah[mt][0], ah[mt][1], ah[mt][2], ah[mt][3], st + AH_OFF + d);
                ldmx4(al[mt][0], al[mt][1], al[mt][2], al[mt][3], st + AL_OFF + d);
            }
            unsigned bh[4][4], bl[4][4];
            #pragma unroll
            for (int np = 0; np < 4; np++) {
                int r = wn * 64 + np * 16 + ((g >> 1) << 3) + l8;
                int c = k0 + ((g & 1) << 3);
                unsigned d = (unsigned)((r * TSTRIDE + c) * 2);
                ldmx4(bh[np][0], bh[np][1], bh[np][2], bh[np][3], st + BH_OFF + d);
                ldmx4(bl[np][0], bl[np][1], bl[np][2], bl[np][3], st + BL_OFF + d);
            }
            // product 1: Ah*Bh  (np varies fastest -> no back-to-back same-acc)
            #pragma unroll
            for (int np = 0; np < 4; np++)
                #pragma unroll
                for (int mt = 0; mt < 2; mt++) {
                    mma16816(acc[mt][np*2][0],   acc[mt][np*2][1],
                             acc[mt][np*2][2],   acc[mt][np*2][3],
                             ah[mt][0], ah[mt][1], ah[mt][2], ah[mt][3],
                             bh[np][0], bh[np][1]);
                    mma16816(acc[mt][np*2+1][0], acc[mt][np*2+1][1],
                             acc[mt][np*2+1][2], acc[mt][np*2+1][3],
                             ah[mt][0], ah[mt][1], ah[mt][2], ah[mt][3],
                             bh[np][2], bh[np][3]);
                }
            // product 2: Al*Bh
            #pragma unroll
            for (int np = 0; np < 4; np++)
                #pragma unroll
                for (int mt = 0; mt < 2; mt++) {
                    mma16816(acc[mt][np*2][0],   acc[mt][np*2][1],
                             acc[mt][np*2][2],   acc[mt][np*2][3],
                             al[mt][0], al[mt][1], al[mt][2], al[mt][3],
                             bh[np][0], bh[np][1]);
                    mma16816(acc[mt][np*2+1][0], acc[mt][np*2+1][1],
                             acc[mt][np*2+1][2], acc[mt][np*2+1][3],
                             al[mt][0], al[mt][1], al[mt][2], al[mt][3],
                             bh[np][2], bh[np][3]);
                }
            // product 3: Ah*Bl
            #pragma unroll
            for (int np = 0; np < 4; np++)
                #pragma unroll
                for (int mt = 0; mt < 2; mt++) {
                    mma16816(acc[mt][np*2][0],   acc[mt][np*2][1],
                             acc[mt][np*2][2],   acc[mt][np*2][3],
                             ah[mt][0], ah[mt][1], ah[mt][2], ah[mt][3],
                             bl[np][0], bl[np][1]);
                    mma16816(acc[mt][np*2+1][0], acc[mt][np*2+1][1],
                             acc[mt][np*2+1][2], acc[mt][np*2+1][3],
                             ah[mt][0], ah[mt][1], ah[mt][2], ah[mt][3],
                             bl[np][2], bl[np][3]);
                }
        }
        __syncthreads();
    }

    // Epilogue: dist = (rn + cn[k]) - 2*dot ; u64 lexicographic argmin
    float rn[4];
    #pragma unroll
    for (int j = 0; j < 4; j++)
        rn[j] = g_rownorm[row0 + wm * 32 + quad + j * 8];

    unsigned long long best[4] = {~0ull, ~0ull, ~0ull, ~0ull};
    #pragma unroll
    for (int nt = 0; nt < 8; nt++) {
        const int cl = wn * 64 + nt * 8 + qt * 2;
        const float cn0 = s_cn[cl], cn1 = s_cn[cl + 1];
        const unsigned kg = (unsigned)(col0 + cl);
        #pragma unroll
        for (int mt = 0; mt < 2; mt++) {
            float d00 = (rn[mt*2]   + cn0) - 2.0f * acc[mt][nt][0];
            float d01 = (rn[mt*2]   + cn1) - 2.0f * acc[mt][nt][1];
            float d10 = (rn[mt*2+1] + cn0) - 2.0f * acc[mt][nt][2];
            float d11 = (rn[mt*2+1] + cn1) - 2.0f * acc[mt][nt][3];
            unsigned long long c00 = ((unsigned long long)__float_as_uint(d00) << 32) | kg;
            unsigned long long c01 = ((unsigned long long)__float_as_uint(d01) << 32) | (kg+1);
            unsigned long long c10 = ((unsigned long long)__float_as_uint(d10) << 32) | kg;
            unsigned long long c11 = ((unsigned long long)__float_as_uint(d11) << 32) | (kg+1);
            if (c00 < best[mt*2])   best[mt*2]   = c00;
            if (c01 < best[mt*2])   best[mt*2]   = c01;
            if (c10 < best[mt*2+1]) best[mt*2+1] = c10;
            if (c11 < best[mt*2+1]) best[mt*2+1] = c11;
        }
    }
    #pragma unroll
    for (int j = 0; j < 4; j++) {
        #pragma unroll
        for (int o = 1; o <= 2; o <<= 1) {
            unsigned long long v = __shfl_xor_sync(0xffffffffu, best[j], o);
            if (v < best[j]) best[j] = v;
        }
    }
    if (qt == 0) {
        #pragma unroll
        for (int j = 0; j < 4; j++)
            s_red[wn * 128 + wm * 32 + quad + j * 8] = best[j];
    }
    __syncthreads();
    if (tid < 128) {
        unsigned long long a0 = s_red[tid], a1 = s_red[128 + tid];
        g_part[(size_t)cb * N_ROWS + row0 + tid] = (a0 < a1) ? a0 : a1;
    }
}

// ---------------------------------------------------------------------------
// merge 4 code-block partials -> index + float index + one_hot 1.0 + loss.
// Loss identity: sum_d (q - lat)^2 = dist + (embnorm[idx] - colnorm[idx])
// ---------------------------------------------------------------------------
__global__ __launch_bounds__(256) void k_merge(float* __restrict__ out) {
    __shared__ double sh[256];
    int n = blockIdx.x * 256 + threadIdx.x;
    unsigned long long m = g_part[n];
    #pragma unroll
    for (int c = 1; c < CBLK; c++) {
        unsigned long long v = g_part[(size_t)c * N_ROWS + n];
        if (v < m) m = v;
    }
    int idx = (int)(m & 0xffffffffu);
    float dist = __uint_as_float((unsigned)(m >> 32));
    g_idx[n] = idx;
    out[IDX_OFF + n] = (float)idx;
    out[OH_OFF + (size_t)n * KCODES + idx] = 1.0f;
    sh[threadIdx.x] = (double)dist + (double)g_embnorm[idx] - (double)g_colnorm[idx];
    __syncthreads();
    for (int o = 128; o > 0; o >>= 1) {
        if (threadIdx.x < o) sh[threadIdx.x] += sh[threadIdx.x + o];
        __syncthreads();
    }
    if (threadIdx.x == 0) g_partial[blockIdx.x] = sh[0];
}

// ---------------------------------------------------------------------------
// quantized writer + finalize folded into block 0
// ---------------------------------------------------------------------------
__global__ __launch_bounds__(256) void k_out(const float* __restrict__ emb,
                                             float* __restrict__ out) {
    if (blockIdx.x == 0) {
        __shared__ double sh[128];
        if (threadIdx.x < 128) sh[threadIdx.x] = g_partial[threadIdx.x];
        __syncthreads();
        for (int o = 64; o > 0; o >>= 1) {
            if (threadIdx.x < o) sh[threadIdx.x] += sh[threadIdx.x + o];
            __syncthreads();
        }
        if (threadIdx.x == 0) {
            double mse = sh[0] / (double)Q_ELEMS;
            out[LOSS_OFF] = (float)(mse * 0.25 + mse);
        }
    }
    const int stride = NB_QO * 256;
    const float4* emb4 = (const float4*)emb;
    float4* out4 = (float4*)out;
    for (int i = blockIdx.x * 256 + threadIdx.x; i < Q_ELEMS / 4; i += stride) {
        int n  = i >> 7;
        int d4 = i & 127;
        out4[i] = emb4[(size_t)g_idx[n] * 128 + d4];
    }
}

// ---------------------------------------------------------------------------
extern "C" void kernel_launch(void* const* d_in, const int* in_sizes, int n_in,
                              void* d_out, int out_size) {
    const float* lat = (const float*)d_in[0];
    const float* emb = (const float*)d_in[1];
    if (n_in >= 2 && in_sizes[0] == KCODES * DIM && in_sizes[1] == Q_ELEMS) {
        const float* t = lat; lat = emb; emb = t;
    }
    float* out = (float*)d_out;

    cudaFuncSetAttribute(k_gemm_argmin,
                         cudaFuncAttributeMaxDynamicSharedMemorySize, SMEM_DYN);

    // zero the one_hot region via graph memset node
    cudaMemsetAsync((void*)(out + OH_OFF), 0,
                    (size_t)N_ROWS * KCODES * sizeof(float), 0);

    k_prep<<<NB_PREP, 256>>>(lat, emb);
    k_gemm_argmin<<<RBLK * CBLK, 256, SMEM_DYN>>>();
    k_merge<<<NB_MG, 256>>>(out);
    k_out<<<NB_QO, 256>>>(emb, out);
}

// round 17
// speedup vs baseline: 1.0595x; 1.0595x over previous
#include <cuda_runtime.h>
#include <cuda_fp16.h>
#include <cstdint>

// ---------------------------------------------------------------------------
// Problem constants
// ---------------------------------------------------------------------------
#define N_ROWS  32768
#define DIM     512
#define KCODES  512
#define Q_ELEMS (N_ROWS * DIM)
#define LOSS_OFF Q_ELEMS
#define OH_OFF   (Q_ELEMS + 1)
#define IDX_OFF  (OH_OFF + N_ROWS * KCODES)

#define NB_QO 2048     // blocks for quantized writer
#define NB_MG 128      // blocks for merge (+loss partials)

// Fused prep kernel block ranges
#define NB_CONVA (N_ROWS / 4)                 // 8192
#define NB_CONVB (KCODES * DIM / 8 / 256)     // 128
#define NB_CN    2                            // colnorm: 2 x 256 = 512 cols
#define NB_EN    (KCODES / 8)                 // 64 (8 rows per block)
#define NB_PREP  (NB_CONVA + NB_CONVB + NB_CN + NB_EN)

// GEMM tiling: M=128 x N=128 per CTA, BK=32, fused 3 products, 2 CTAs/SM.
#define MT   128
#define NTC  128
#define BK   32
#define NKCH (DIM / BK)          // 16
#define RBLK (N_ROWS / MT)       // 256
#define CBLK (KCODES / NTC)      // 4

#define TSTRIDE 40               // 32 + 8 pad (rows stride 80B, conflict-free)
#define AT_B   (MT * TSTRIDE * 2)        // 10240
#define AH_OFF 0
#define AL_OFF AT_B
#define BH_OFF (2 * AT_B)
#define BL_OFF (3 * AT_B)
#define STAGE_B (4 * AT_B)               // 40960
#define CN_OFF  (2 * STAGE_B)            // 81920
#define RED_OFF (CN_OFF + 512)           // 82432
#define SMEM_DYN (RED_OFF + 2 * 128 * 8) // 84480  (2 CTAs/SM)

// one_hot zero-fill inside the GEMM: 16M floats / 1024 CTAs = 16384 per CTA
#define OH_PER_CTA 16384

// ---------------------------------------------------------------------------
// Device scratch
// ---------------------------------------------------------------------------
__device__ __align__(16) __half g_Ah[(size_t)N_ROWS * DIM];
__device__ __align__(16) __half g_Al[(size_t)N_ROWS * DIM];
__device__ __align__(16) __half g_Bh[(size_t)KCODES * DIM];
__device__ __align__(16) __half g_Bl[(size_t)KCODES * DIM];
__device__ float  g_rownorm[N_ROWS];
__device__ float  g_colnorm[KCODES];   // dim=0 norm (reference's buggy norm)
__device__ float  g_embnorm[KCODES];   // dim=1 norm (true row norm, loss only)
__device__ unsigned long long g_part[(size_t)CBLK * N_ROWS];
__device__ int    g_idx[N_ROWS];
__device__ double g_partial[NB_MG];

// ---------------------------------------------------------------------------
// PTX helpers (compute_100-legal)
// ---------------------------------------------------------------------------
__device__ __forceinline__ unsigned smem_u32(const void* p) {
    unsigned a;
    asm("{ .reg .u64 t; cvta.to.shared.u64 t, %1; cvt.u32.u64 %0, t; }" : "=r"(a) : "l"(p));
    return a;
}
__device__ __forceinline__ void cp16(unsigned dst, const void* src) {
    asm volatile("cp.async.cg.shared.global [%0], [%1], 16;" :: "r"(dst), "l"(src));
}
__device__ __forceinline__ void cp_commit() { asm volatile("cp.async.commit_group;"); }
__device__ __forceinline__ void cp_wait1()  { asm volatile("cp.async.wait_group 1;"); }
__device__ __forceinline__ void cp_wait0()  { asm volatile("cp.async.wait_group 0;"); }

__device__ __forceinline__ void ldmx4(unsigned& r0, unsigned& r1, unsigned& r2, unsigned& r3,
                                      unsigned addr) {
    asm volatile("ldmatrix.sync.aligned.m8n8.x4.shared.b16 {%0,%1,%2,%3}, [%4];"
                 : "=r"(r0), "=r"(r1), "=r"(r2), "=r"(r3) : "r"(addr));
}
__device__ __forceinline__ void mma16816(float& c0, float& c1, float& c2, float& c3,
                                         unsigned a0, unsigned a1, unsigned a2, unsigned a3,
                                         unsigned b0, unsigned b1) {
    asm volatile("mma.sync.aligned.m16n8k16.row.col.f32.f16.f16.f32 "
                 "{%0,%1,%2,%3}, {%4,%5,%6,%7}, {%8,%9}, {%0,%1,%2,%3};"
                 : "+f"(c0), "+f"(c1), "+f"(c2), "+f"(c3)
                 : "r"(a0), "r"(a1), "r"(a2), "r"(a3), "r"(b0), "r"(b1));
}

// ---------------------------------------------------------------------------
// fp32 -> (fp16 hi, fp16 lo)
// ---------------------------------------------------------------------------
__device__ __forceinline__ unsigned pack2(float a, float b) {
    unsigned short ha = __half_as_ushort(__float2half_rn(a));
    unsigned short hb = __half_as_ushort(__float2half_rn(b));
    return (unsigned)ha | ((unsigned)hb << 16);
}

// ---------------------------------------------------------------------------
// Fused prep: convA+rownorm | convertB | colnorm | embnorm by block range.
// Bodies byte-identical to the round-15 passing kernel.
// ---------------------------------------------------------------------------
__global__ __launch_bounds__(256) void k_prep(const float* __restrict__ lat,
                                              const float* __restrict__ emb) {
    __shared__ float sx[4][DIM];
    const int tid = threadIdx.x;
    const int bx  = blockIdx.x;

    if (bx < NB_CONVA) {
        const int nl  = tid >> 6;
        const int c   = (tid & 63) * 8;
        const size_t n = (size_t)bx * 4 + nl;
        const size_t off = n * DIM + c;

        const float4* s4 = (const float4*)(lat + off);
        float4 v0 = s4[0], v1 = s4[1];
        float x[8] = {v0.x, v0.y, v0.z, v0.w, v1.x, v1.y, v1.z, v1.w};
        float l[8];
        #pragma unroll
        for (int j = 0; j < 8; j++) {
            sx[nl][c + j] = x[j];
            l[j] = x[j] - __half2float(__float2half_rn(x[j]));
        }
        uint4 hi = make_uint4(pack2(x[0], x[1]), pack2(x[2], x[3]),
                              pack2(x[4], x[5]), pack2(x[6], x[7]));
        uint4 lo = make_uint4(pack2(l[0], l[1]), pack2(l[2], l[3]),
                              pack2(l[4], l[5]), pack2(l[6], l[7]));
        *(uint4*)(g_Ah + off) = hi;
        *(uint4*)(g_Al + off) = lo;

        __syncthreads();
        const int wid  = tid >> 5;
        const int lane = tid & 31;
        if (wid < 4) {
            float s = 0.f;
            for (int t = lane; t < DIM; t += 32) {
                float v = sx[wid][t];
                s += v * v;
            }
            #pragma unroll
            for (int o = 16; o > 0; o >>= 1) s += __shfl_xor_sync(0xffffffffu, s, o);
            if (lane == 0) g_rownorm[(size_t)bx * 4 + wid] = s;
        }
    } else if (bx < NB_CONVA + NB_CONVB) {
        size_t g = (size_t)(bx - NB_CONVA) * 256 + tid;
        size_t off = g * 8;
        const float4* s4 = (const float4*)(emb + off);
        float4 v0 = s4[0], v1 = s4[1];
        float x[8] = {v0.x, v0.y, v0.z, v0.w, v1.x, v1.y, v1.z, v1.w};
        float l[8];
        #pragma unroll
        for (int j = 0; j < 8; j++)
            l[j] = x[j] - __half2float(__float2half_rn(x[j]));
        uint4 hi = make_uint4(pack2(x[0], x[1]), pack2(x[2], x[3]),
                              pack2(x[4], x[5]), pack2(x[6], x[7]));
        uint4 lo = make_uint4(pack2(l[0], l[1]), pack2(l[2], l[3]),
                              pack2(l[4], l[5]), pack2(l[6], l[7]));
        *(uint4*)(g_Bh + off) = hi;
        *(uint4*)(g_Bl + off) = lo;
    } else if (bx < NB_CONVA + NB_CONVB + NB_CN) {
        int k = (bx - NB_CONVA - NB_CONVB) * 256 + tid;
        float s = 0.f;
        for (int j = 0; j < KCODES; j++) {
            float v = emb[(size_t)j * DIM + k];
            s += v * v;
        }
        g_colnorm[k] = s;
    } else {
        const int wid  = tid >> 5;
        const int lane = tid & 31;
        int warp = (bx - NB_CONVA - NB_CONVB - NB_CN) * 8 + wid;
        const float* e = emb + (size_t)warp * DIM;
        float s = 0.f;
        for (int t = lane; t < DIM; t += 32) {
            float v = e[t];
            s += v * v;
        }
        #pragma unroll
        for (int o = 16; o > 0; o >>= 1) s += __shfl_xor_sync(0xffffffffu, s, o);
        if (lane == 0) g_embnorm[warp] = s;
    }
}

// ---------------------------------------------------------------------------
// GEMM + argmin: 128x128 tile, BK=32, 2 CTAs/SM (round-15 proven MMA order).
// Additionally zero-fills this CTA's 16384-float slice of one_hot, 4 scalar
// stores/thread per K-chunk (DRAM sits at 5% here — effectively free).
// ---------------------------------------------------------------------------
__global__ __launch_bounds__(256, 2) void k_gemm_argmin(float* __restrict__ out) {
    extern __shared__ char smem[];
    const unsigned S = smem_u32(smem);

    const int tid  = threadIdx.x;
    const int wid  = tid >> 5;
    const int lane = tid & 31;
    const int wm   = wid >> 1;
    const int wn   = wid & 1;
    const int quad = lane >> 2;
    const int qt   = lane & 3;
    const int cb   = blockIdx.x & 3;
    const int rb   = blockIdx.x >> 2;
    const int row0 = rb * MT;
    const int col0 = cb * NTC;

    float* s_cn = (float*)(smem + CN_OFF);
    unsigned long long* s_red = (unsigned long long*)(smem + RED_OFF);

    if (tid < NTC) s_cn[tid] = g_colnorm[col0 + tid];

    const __half* Ah = g_Ah + (size_t)row0 * DIM;
    const __half* Al = g_Al + (size_t)row0 * DIM;
    const __half* Bh = g_Bh + (size_t)col0 * DIM;
    const __half* Bl = g_Bl + (size_t)col0 * DIM;

    // one_hot zero slice for this CTA
    float* oh = out + OH_OFF + (size_t)blockIdx.x * OH_PER_CTA;

    float acc[2][8][4];
    #pragma unroll
    for (int mt = 0; mt < 2; mt++)
        #pragma unroll
        for (int nt = 0; nt < 8; nt++)
            #pragma unroll
            for (int j = 0; j < 4; j++) acc[mt][nt][j] = 0.f;

    auto load_chunk = [&](int i, int buf) {
        const int kc = i * BK;
        const unsigned st = S + buf * STAGE_B;
        #pragma unroll
        for (int j = 0; j < 2; j++) {
            int id = tid + j * 256;          // 0..511
            int r = id >> 2, c = (id & 3) * 8;
            unsigned d = (unsigned)((r * TSTRIDE + c) * 2);
            cp16(st + AH_OFF + d, Ah + (size_t)r * DIM + kc + c);
            cp16(st + AL_OFF + d, Al + (size_t)r * DIM + kc + c);
            cp16(st + BH_OFF + d, Bh + (size_t)r * DIM + kc + c);
            cp16(st + BL_OFF + d, Bl + (size_t)r * DIM + kc + c);
        }
        cp_commit();
    };

    load_chunk(0, 0);

    const int g  = lane >> 3;
    const int l8 = lane & 7;

    for (int i = 0; i < NKCH; i++) {
        const int buf = i & 1;
        if (i + 1 < NKCH) { load_chunk(i + 1, buf ^ 1); cp_wait1(); }
        else             { cp_wait0(); }
        __syncthreads();

        // zero-fill 4*256 floats of this CTA's one_hot slice per chunk
        #pragma unroll
        for (int z = 0; z < 4; z++)
            oh[(i * 4 + z) * 256 + tid] = 0.0f;

        const unsigned st = S + buf * STAGE_B;

        #pragma unroll
        for (int ks = 0; ks < 2; ks++) {
            const int k0 = ks * 16;
            unsigned ah[2][4], al[2][4];
            #pragma unroll
            for (int mt = 0; mt < 2; mt++) {
                int r = wm * 32 + mt * 16 + ((g & 1) << 3) + l8;
                int c = k0 + ((g >> 1) << 3);
                unsigned d = (unsigned)((r * TSTRIDE + c) * 2);
                ldmx4(ah[mt][0], ah[mt][1], ah[mt][2], ah[mt][3], st + AH_OFF + d);
                ldmx4(al[mt][0], al[mt][1], al[mt][2], al[mt][3], st + AL_OFF + d);
            }
            #pragma unroll
            for (int np = 0; np < 4; np++) {
                int r = wn * 64 + np * 16 + ((g >> 1) << 3) + l8;
                int c = k0 + ((g & 1) << 3);
                unsigned d = (unsigned)((r * TSTRIDE + c) * 2);
                unsigned bh[4], bl[4];
                ldmx4(bh[0], bh[1], bh[2], bh[3], st + BH_OFF + d);
                ldmx4(bl[0], bl[1], bl[2], bl[3], st + BL_OFF + d);
                #pragma unroll
                for (int mt = 0; mt < 2; mt++) {
                    mma16816(acc[mt][np*2][0],   acc[mt][np*2][1],
                             acc[mt][np*2][2],   acc[mt][np*2][3],
                             ah[mt][0], ah[mt][1], ah[mt][2], ah[mt][3], bh[0], bh[1]);
                    mma16816(acc[mt][np*2+1][0], acc[mt][np*2+1][1],
                             acc[mt][np*2+1][2], acc[mt][np*2+1][3],
                             ah[mt][0], ah[mt][1], ah[mt][2], ah[mt][3], bh[2], bh[3]);
                    mma16816(acc[mt][np*2][0],   acc[mt][np*2][1],
                             acc[mt][np*2][2],   acc[mt][np*2][3],
                             al[mt][0], al[mt][1], al[mt][2], al[mt][3], bh[0], bh[1]);
                    mma16816(acc[mt][np*2+1][0], acc[mt][np*2+1][1],
                             acc[mt][np*2+1][2], acc[mt][np*2+1][3],
                             al[mt][0], al[mt][1], al[mt][2], al[mt][3], bh[2], bh[3]);
                    mma16816(acc[mt][np*2][0],   acc[mt][np*2][1],
                             acc[mt][np*2][2],   acc[mt][np*2][3],
                             ah[mt][0], ah[mt][1], ah[mt][2], ah[mt][3], bl[0], bl[1]);
                    mma16816(acc[mt][np*2+1][0], acc[mt][np*2+1][1],
                             acc[mt][np*2+1][2], acc[mt][np*2+1][3],
                             ah[mt][0], ah[mt][1], ah[mt][2], ah[mt][3], bl[2], bl[3]);
                }
            }
        }
        __syncthreads();
    }

    // Epilogue: dist = (rn + cn[k]) - 2*dot ; u64 lexicographic argmin
    float rn[4];
    #pragma unroll
    for (int j = 0; j < 4; j++)
        rn[j] = g_rownorm[row0 + wm * 32 + quad + j * 8];

    unsigned long long best[4] = {~0ull, ~0ull, ~0ull, ~0ull};
    #pragma unroll
    for (int nt = 0; nt < 8; nt++) {
        const int cl = wn * 64 + nt * 8 + qt * 2;
        const float cn0 = s_cn[cl], cn1 = s_cn[cl + 1];
        const unsigned kg = (unsigned)(col0 + cl);
        #pragma unroll
        for (int mt = 0; mt < 2; mt++) {
            float d00 = (rn[mt*2]   + cn0) - 2.0f * acc[mt][nt][0];
            float d01 = (rn[mt*2]   + cn1) - 2.0f * acc[mt][nt][1];
            float d10 = (rn[mt*2+1] + cn0) - 2.0f * acc[mt][nt][2];
            float d11 = (rn[mt*2+1] + cn1) - 2.0f * acc[mt][nt][3];
            unsigned long long c00 = ((unsigned long long)__float_as_uint(d00) << 32) | kg;
            unsigned long long c01 = ((unsigned long long)__float_as_uint(d01) << 32) | (kg+1);
            unsigned long long c10 = ((unsigned long long)__float_as_uint(d10) << 32) | kg;
            unsigned long long c11 = ((unsigned long long)__float_as_uint(d11) << 32) | (kg+1);
            if (c00 < best[mt*2])   best[mt*2]   = c00;
            if (c01 < best[mt*2])   best[mt*2]   = c01;
            if (c10 < best[mt*2+1]) best[mt*2+1] = c10;
            if (c11 < best[mt*2+1]) best[mt*2+1] = c11;
        }
    }
    #pragma unroll
    for (int j = 0; j < 4; j++) {
        #pragma unroll
        for (int o = 1; o <= 2; o <<= 1) {
            unsigned long long v = __shfl_xor_sync(0xffffffffu, best[j], o);
            if (v < best[j]) best[j] = v;
        }
    }
    if (qt == 0) {
        #pragma unroll
        for (int j = 0; j < 4; j++)
            s_red[wn * 128 + wm * 32 + quad + j * 8] = best[j];
    }
    __syncthreads();
    if (tid < 128) {
        unsigned long long a0 = s_red[tid], a1 = s_red[128 + tid];
        g_part[(size_t)cb * N_ROWS + row0 + tid] = (a0 < a1) ? a0 : a1;
    }
}

// ---------------------------------------------------------------------------
// merge 4 code-block partials -> index + float index + one_hot 1.0 + loss.
// Loss identity: sum_d (q - lat)^2 = dist + (embnorm[idx] - colnorm[idx])
// ---------------------------------------------------------------------------
__global__ __launch_bounds__(256) void k_merge(float* __restrict__ out) {
    __shared__ double sh[256];
    int n = blockIdx.x * 256 + threadIdx.x;
    unsigned long long m = g_part[n];
    #pragma unroll
    for (int c = 1; c < CBLK; c++) {
        unsigned long long v = g_part[(size_t)c * N_ROWS + n];
        if (v < m) m = v;
    }
    int idx = (int)(m & 0xffffffffu);
    float dist = __uint_as_float((unsigned)(m >> 32));
    g_idx[n] = idx;
    out[IDX_OFF + n] = (float)idx;
    out[OH_OFF + (size_t)n * KCODES + idx] = 1.0f;
    sh[threadIdx.x] = (double)dist + (double)g_embnorm[idx] - (double)g_colnorm[idx];
    __syncthreads();
    for (int o = 128; o > 0; o >>= 1) {
        if (threadIdx.x < o) sh[threadIdx.x] += sh[threadIdx.x + o];
        __syncthreads();
    }
    if (threadIdx.x == 0) g_partial[blockIdx.x] = sh[0];
}

// ---------------------------------------------------------------------------
// quantized writer + finalize folded into block 0
// ---------------------------------------------------------------------------
__global__ __launch_bounds__(256) void k_out(const float* __restrict__ emb,
                                             float* __restrict__ out) {
    if (blockIdx.x == 0) {
        __shared__ double sh[128];
        if (threadIdx.x < 128) sh[threadIdx.x] = g_partial[threadIdx.x];
        __syncthreads();
        for (int o = 64; o > 0; o >>= 1) {
            if (threadIdx.x < o) sh[threadIdx.x] += sh[threadIdx.x + o];
            __syncthreads();
        }
        if (threadIdx.x == 0) {
            double mse = sh[0] / (double)Q_ELEMS;
            out[LOSS_OFF] = (float)(mse * 0.25 + mse);
        }
    }
    const int stride = NB_QO * 256;
    const float4* emb4 = (const float4*)emb;
    float4* out4 = (float4*)out;
    for (int i = blockIdx.x * 256 + threadIdx.x; i < Q_ELEMS / 4; i += stride) {
        int n  = i >> 7;
        int d4 = i & 127;
        out4[i] = emb4[(size_t)g_idx[n] * 128 + d4];
    }
}

// ---------------------------------------------------------------------------
extern "C" void kernel_launch(void* const* d_in, const int* in_sizes, int n_in,
                              void* d_out, int out_size) {
    const float* lat = (const float*)d_in[0];
    const float* emb = (const float*)d_in[1];
    if (n_in >= 2 && in_sizes[0] == KCODES * DIM && in_sizes[1] == Q_ELEMS) {
        const float* t = lat; lat = emb; emb = t;
    }
    float* out = (float*)d_out;

    cudaFuncSetAttribute(k_gemm_argmin,
                         cudaFuncAttributeMaxDynamicSharedMemorySize, SMEM_DYN);

    k_prep<<<NB_PREP, 256>>>(lat, emb);
    k_gemm_argmin<<<RBLK * CBLK, 256, SMEM_DYN>>>(out);
    k_merge<<<NB_MG, 256>>>(out);
    k_out<<<NB_QO, 256>>>(emb, out);
}